// round 7
// baseline (speedup 1.0000x reference)
#include <cuda_runtime.h>
#include <cuda_fp16.h>
#include <cstdint>
#include <math.h>

#define D_MODEL 2048
#define NHEADS 16
#define DK 128
#define MAX_S 2048
#define MAX_M 4096
#define W_ELEMS ((size_t)D_MODEL * D_MODEL)

// ---------------- scratch (static device globals; no allocation) ----------------
__device__ __half g_Wt[4 * W_ELEMS];                 // [4][f][d] transposed fp16 weights (q,k,v,o)
__device__ __half g_xh[(size_t)MAX_M * D_MODEL];     // fp16 copy of x
__device__ __half g_Qh[(size_t)MAX_M * D_MODEL];     // [B,H,S,DK] (scale folded)
__device__ __half g_Kh[(size_t)MAX_M * D_MODEL];
__device__ __half g_Vh[(size_t)MAX_M * D_MODEL];
__device__ __half g_attnH[(size_t)MAX_M * D_MODEL];  // [M, D_MODEL]
__device__ float g_cosT[MAX_S * (DK / 2)];
__device__ float g_sinT[MAX_S * (DK / 2)];

// ---------------- asm helpers ----------------
__device__ __forceinline__ void ldsm4(uint32_t* r, uint32_t addr) {
    asm volatile("ldmatrix.sync.aligned.m8n8.x4.shared.b16 {%0,%1,%2,%3}, [%4];"
                 : "=r"(r[0]), "=r"(r[1]), "=r"(r[2]), "=r"(r[3]) : "r"(addr));
}
__device__ __forceinline__ void ldsm4t(uint32_t* r, uint32_t addr) {
    asm volatile("ldmatrix.sync.aligned.m8n8.x4.trans.shared.b16 {%0,%1,%2,%3}, [%4];"
                 : "=r"(r[0]), "=r"(r[1]), "=r"(r[2]), "=r"(r[3]) : "r"(addr));
}
__device__ __forceinline__ void mma16816(float* d, const uint32_t* a, uint32_t b0, uint32_t b1) {
    asm volatile(
        "mma.sync.aligned.m16n8k16.row.col.f32.f16.f16.f32 "
        "{%0,%1,%2,%3}, {%4,%5,%6,%7}, {%8,%9}, {%0,%1,%2,%3};"
        : "+f"(d[0]), "+f"(d[1]), "+f"(d[2]), "+f"(d[3])
        : "r"(a[0]), "r"(a[1]), "r"(a[2]), "r"(a[3]), "r"(b0), "r"(b1));
}
__device__ __forceinline__ void cp16(uint32_t saddr, const void* gptr) {
    asm volatile("cp.async.cg.shared.global [%0], [%1], 16;" :: "r"(saddr), "l"(gptr));
}
__device__ __forceinline__ void cp_commit() { asm volatile("cp.async.commit_group;"); }
#define CP_WAIT(N) asm volatile("cp.async.wait_group %0;" :: "n"(N))
__device__ __forceinline__ uint32_t packh2(float a, float b) {
    __half2 h = __floats2half2_rn(a, b);
    return *reinterpret_cast<uint32_t*>(&h);
}

// ---------------- RoPE table ----------------
__global__ void rope_table_kernel(const int* __restrict__ pos, int S) {
    int idx = blockIdx.x * blockDim.x + threadIdx.x;
    if (idx >= S * (DK / 2)) return;
    int s = idx / (DK / 2);
    int i = idx % (DK / 2);
    float invf = (float)pow(10000.0, -(double)(2 * i) / (double)DK);
    float ang = (float)pos[s] * invf;
    g_cosT[idx] = cosf(ang);
    g_sinT[idx] = sinf(ang);
}

// ---------------- converters ----------------
__global__ void convert_x_kernel(const float* __restrict__ x, int n) {
    int i = (blockIdx.x * blockDim.x + threadIdx.x) * 4;
    if (i >= n) return;
    float4 v = *reinterpret_cast<const float4*>(x + i);
    uint2 u = {packh2(v.x, v.y), packh2(v.z, v.w)};
    *reinterpret_cast<uint2*>(&g_xh[i]) = u;
}

__global__ void transpose_w_kernel(const float* __restrict__ Wq, const float* __restrict__ Wk,
                                   const float* __restrict__ Wv, const float* __restrict__ Wo) {
    __shared__ float t[32][33];
    const int z = blockIdx.z;
    const float* W = (z == 0) ? Wq : (z == 1) ? Wk : (z == 2) ? Wv : Wo;
    __half* dst = g_Wt + (size_t)z * W_ELEMS;
    int x0 = blockIdx.x * 32, y0 = blockIdx.y * 32;
    int tx = threadIdx.x, ty = threadIdx.y;
#pragma unroll
    for (int i = 0; i < 4; i++)
        t[ty + i * 8][tx] = W[(size_t)(y0 + ty + i * 8) * D_MODEL + x0 + tx];
    __syncthreads();
#pragma unroll
    for (int i = 0; i < 4; i++)
        dst[(size_t)(x0 + ty + i * 8) * D_MODEL + y0 + tx] = __float2half(t[tx][ty + i * 8]);
}

// ---------------- GEMM: 128x256 CTA tile, 64x64 warp tiles, 3-stage cp.async ----
// Crossbar math: 64x64 warp tiles -> smem reads 0.0625 B/MAC (+0.025 store) vs
// 0.129 B/MAC at 32x64; tensor pipe (0.125 B/MAC parity) becomes the limiter.
#define SA 72                      // halves per smem row (64 data + 8 pad); 144B stride
#define GA_STG (128 * SA * 2)      // A stage bytes (18432)
#define GB_STG (256 * SA * 2)      // B stage bytes (36864)
#define G_STG (GA_STG + GB_STG)    // 55296
#define G_SMEM (3 * G_STG)         // 165888

__global__ __launch_bounds__(256, 1) void gemm_f16_kernel(float* __restrict__ outF, int M,
                                                          int S, int mode_in) {
    extern __shared__ __align__(16) unsigned char smraw[];
    uint32_t sm = (uint32_t)__cvta_generic_to_shared(smraw);

    const int mode = (mode_in < 0) ? (int)blockIdx.z : mode_in;
    const __half* Ag = (mode_in < 0) ? g_xh : g_attnH;
    const __half* Bg = g_Wt + (size_t)mode * W_ELEMS;  // [n][k] fp16
    const int bm = blockIdx.y * 128;
    const int bn = blockIdx.x * 256;
    const int tid = threadIdx.x;
    const int lane = tid & 31, wid = tid >> 5;
    const int wm = wid & 1, wn = wid >> 1;  // 2 warps along M (64 rows), 4 along N (64 cols)
    const int lr = lane >> 2, lc = lane & 3;

    // ldmatrix lane address components
    const int a_row = (lane & 7) + ((lane >> 3) & 1) * 8;
    const int a_ch = (lane >> 4) * 8;
    int aoff[4];
#pragma unroll
    for (int mt = 0; mt < 4; mt++) aoff[mt] = ((wm * 64 + mt * 16 + a_row) * SA + a_ch) * 2;
    const int b_row = (lane >> 4) * 8 + (lane & 7);
    const int b_k = ((lane >> 3) & 1) * 8;
    int boff[4];
#pragma unroll
    for (int bt = 0; bt < 4; bt++) boff[bt] = ((wn * 64 + bt * 16 + b_row) * SA + b_k) * 2;

    float acc[4][8][4];
#pragma unroll
    for (int i = 0; i < 4; i++)
#pragma unroll
        for (int j = 0; j < 8; j++)
#pragma unroll
            for (int k = 0; k < 4; k++) acc[i][j][k] = 0.f;

    auto prefetch = [&](int stage, int kt) {
        uint32_t aB = sm + stage * G_STG;
        uint32_t bB = aB + GA_STG;
        const __half* Ap = Ag + (size_t)bm * D_MODEL + kt * 64;
        const __half* Bp = Bg + (size_t)bn * D_MODEL + kt * 64;
#pragma unroll
        for (int i = 0; i < 4; i++) {  // A: 128 rows x 8 chunks of 16B
            int idx = tid + i * 256;
            int r = idx >> 3, c = (idx & 7) * 8;
            cp16(aB + (r * SA + c) * 2, Ap + (size_t)r * D_MODEL + c);
        }
#pragma unroll
        for (int i = 0; i < 8; i++) {  // B: 256 rows x 8 chunks
            int idx = tid + i * 256;
            int r = idx >> 3, c = (idx & 7) * 8;
            cp16(bB + (r * SA + c) * 2, Bp + (size_t)r * D_MODEL + c);
        }
    };

    prefetch(0, 0);
    cp_commit();
    prefetch(1, 1);
    cp_commit();

    for (int kt = 0; kt < 32; kt++) {
        CP_WAIT(1);
        __syncthreads();
        if (kt + 2 < 32) prefetch((kt + 2) % 3, kt + 2);
        cp_commit();

        uint32_t aB = sm + (kt % 3) * G_STG;
        uint32_t bB = aB + GA_STG;
#pragma unroll
        for (int kk = 0; kk < 4; kk++) {
            uint32_t a[4][4];
#pragma unroll
            for (int mt = 0; mt < 4; mt++) ldsm4(a[mt], aB + aoff[mt] + kk * 32);
#pragma unroll
            for (int bt = 0; bt < 4; bt++) {
                uint32_t b[4];
                ldsm4(b, bB + boff[bt] + kk * 32);
#pragma unroll
                for (int mt = 0; mt < 4; mt++) {
                    mma16816(acc[mt][2 * bt], a[mt], b[0], b[1]);
                    mma16816(acc[mt][2 * bt + 1], a[mt], b[2], b[3]);
                }
            }
        }
    }

    // epilogue: c0,c1 = columns (2lc, 2lc+1) -> RoPE pair
#pragma unroll
    for (int mt = 0; mt < 4; mt++) {
#pragma unroll
        for (int nt = 0; nt < 8; nt++) {
#pragma unroll
            for (int half = 0; half < 2; half++) {
                int m = bm + wm * 64 + mt * 16 + lr + half * 8;
                int f = bn + wn * 64 + nt * 8 + lc * 2;
                float c0 = acc[mt][nt][half * 2];
                float c1 = acc[mt][nt][half * 2 + 1];
                if (mode == 3) {
                    *reinterpret_cast<float2*>(outF + (size_t)m * D_MODEL + f) =
                        make_float2(c0, c1);
                } else {
                    int b = m / S, s = m - b * S;
                    int h = f >> 7, d = f & (DK - 1);
                    float o0 = c0, o1 = c1;
                    if (mode < 2) {
                        int i = d >> 1;
                        float cs = g_cosT[s * (DK / 2) + i];
                        float sn = g_sinT[s * (DK / 2) + i];
                        o0 = c0 * cs - c1 * sn;
                        o1 = c0 * sn + c1 * cs;
                        if (mode == 0) {  // fold 1/sqrt(DK) into Q
                            o0 *= 0.08838834764831845f;
                            o1 *= 0.08838834764831845f;
                        }
                    }
                    __half* dst = ((mode == 0) ? g_Qh : (mode == 1) ? g_Kh : g_Vh) +
                                  ((size_t)(b * NHEADS + h) * S + s) * DK + d;
                    *reinterpret_cast<uint32_t*>(dst) = packh2(o0, o1);
                }
            }
        }
    }
}

// ---------------- Flash attention: Br=128, Bc=64, fp16, reg-resident P ----------------
#define FSV 136                      // halves per smem row (128 data + 8 pad); 272B
#define Q_HALVES (128 * FSV)
#define KV_STAGE_H (64 * FSV)
#define FA_SMEM ((Q_HALVES + 6 * KV_STAGE_H) * 2)  // 139264

__global__ __launch_bounds__(256, 1) void fa_kernel(int S) {
    extern __shared__ __align__(16) unsigned char smraw[];
    uint32_t sm = (uint32_t)__cvta_generic_to_shared(smraw);

    const int bh = blockIdx.y;
    const int qtile = blockIdx.x;
    const int qbase = qtile * 128;
    const __half* Qp = g_Qh + (size_t)bh * S * DK;
    const __half* Kp = g_Kh + (size_t)bh * S * DK;
    const __half* Vp = g_Vh + (size_t)bh * S * DK;

    const int tid = threadIdx.x, lane = tid & 31, wid = tid >> 5;
    const int lr = lane >> 2, lc = lane & 3;

    // Q tile -> smem via cp.async (group 0)
#pragma unroll
    for (int i = 0; i < 8; i++) {
        int idx = tid + i * 256;
        int r = idx >> 4, c = (idx & 15) * 8;
        cp16(sm + (r * FSV + c) * 2, Qp + (size_t)(qbase + r) * DK + c);
    }
    cp_commit();

    auto prefetchKV = [&](int j, int stage) {
        uint32_t kB = sm + (Q_HALVES + stage * KV_STAGE_H) * 2;
        uint32_t vB = sm + (Q_HALVES + (3 + stage) * KV_STAGE_H) * 2;
        const __half* Kt = Kp + (size_t)(j * 64) * DK;
        const __half* Vt = Vp + (size_t)(j * 64) * DK;
#pragma unroll
        for (int i = 0; i < 4; i++) {
            int idx = tid + i * 256;
            int r = idx >> 4, c = (idx & 15) * 8;
            cp16(kB + (r * FSV + c) * 2, Kt + (size_t)r * DK + c);
            cp16(vB + (r * FSV + c) * 2, Vt + (size_t)r * DK + c);
        }
    };

    prefetchKV(0, 0);
    cp_commit();
    prefetchKV(1, 1);
    cp_commit();

    CP_WAIT(2);  // Q resident
    __syncthreads();

    // preload Q fragments (reused across all kv tiles)
    uint32_t Qf[8][4];
    {
        int r = wid * 16 + (lane & 7) + ((lane >> 3) & 1) * 8;
        int ch = (lane >> 4) * 8;
#pragma unroll
        for (int kk = 0; kk < 8; kk++) ldsm4(Qf[kk], sm + (r * FSV + ch + kk * 16) * 2);
    }

    float O[16][4];
#pragma unroll
    for (int i = 0; i < 16; i++)
#pragma unroll
        for (int j = 0; j < 4; j++) O[i][j] = 0.f;
    float m0 = -INFINITY, m1 = -INFINITY, l0 = 0.f, l1 = 0.f;

    const int nkv = 2 * qtile + 2;
    const int q0 = qbase + wid * 16 + lr;

    // ldmatrix lane components
    const int kb_row = (lane >> 4) * 8 + (lane & 7);        // K: key row
    const int kb_k = ((lane >> 3) & 1) * 8;                 // K: d offset
    const int v_krow = (lane & 7) + ((lane >> 3) & 1) * 8;  // V: key row within 16
    const int v_dch = (lane >> 4) * 8;                      // V: d chunk offset

    for (int j = 0; j < nkv; j++) {
        CP_WAIT(1);
        __syncthreads();
        if (j + 2 < nkv) prefetchKV(j + 2, (j + 2) % 3);
        cp_commit();

        const int stage = j % 3;
        const uint32_t kB = sm + (Q_HALVES + stage * KV_STAGE_H) * 2;
        const uint32_t vB = sm + (Q_HALVES + (3 + stage) * KV_STAGE_H) * 2;
        const int kv0 = j * 64;

        // S = Q K^T
        float Sa[8][4];
#pragma unroll
        for (int i = 0; i < 8; i++)
#pragma unroll
            for (int t = 0; t < 4; t++) Sa[i][t] = 0.f;
#pragma unroll
        for (int kk = 0; kk < 8; kk++) {
#pragma unroll
            for (int bt = 0; bt < 4; bt++) {
                uint32_t b[4];
                ldsm4(b, kB + ((bt * 16 + kb_row) * FSV + kb_k + kk * 16) * 2);
                mma16816(Sa[2 * bt], Qf[kk], b[0], b[1]);
                mma16816(Sa[2 * bt + 1], Qf[kk], b[2], b[3]);
            }
        }

        // causal mask (only last two kv tiles overlap the diagonal)
        if (j >= nkv - 2) {
#pragma unroll
            for (int nt = 0; nt < 8; nt++) {
                int key = kv0 + nt * 8 + lc * 2;
                if (key > q0) Sa[nt][0] = -INFINITY;
                if (key + 1 > q0) Sa[nt][1] = -INFINITY;
                if (key > q0 + 8) Sa[nt][2] = -INFINITY;
                if (key + 1 > q0 + 8) Sa[nt][3] = -INFINITY;
            }
        }

        // online softmax (fp32)
        float mx0 = -INFINITY, mx1 = -INFINITY;
#pragma unroll
        for (int nt = 0; nt < 8; nt++) {
            mx0 = fmaxf(mx0, fmaxf(Sa[nt][0], Sa[nt][1]));
            mx1 = fmaxf(mx1, fmaxf(Sa[nt][2], Sa[nt][3]));
        }
        mx0 = fmaxf(mx0, __shfl_xor_sync(0xffffffffu, mx0, 1));
        mx0 = fmaxf(mx0, __shfl_xor_sync(0xffffffffu, mx0, 2));
        mx1 = fmaxf(mx1, __shfl_xor_sync(0xffffffffu, mx1, 1));
        mx1 = fmaxf(mx1, __shfl_xor_sync(0xffffffffu, mx1, 2));
        float mn0 = fmaxf(m0, mx0), mn1 = fmaxf(m1, mx1);
        float al0 = __expf(m0 - mn0), al1 = __expf(m1 - mn1);
        m0 = mn0;
        m1 = mn1;
        float rs0 = 0.f, rs1 = 0.f;
#pragma unroll
        for (int nt = 0; nt < 8; nt++) {
            Sa[nt][0] = __expf(Sa[nt][0] - mn0);
            Sa[nt][1] = __expf(Sa[nt][1] - mn0);
            Sa[nt][2] = __expf(Sa[nt][2] - mn1);
            Sa[nt][3] = __expf(Sa[nt][3] - mn1);
            rs0 += Sa[nt][0] + Sa[nt][1];
            rs1 += Sa[nt][2] + Sa[nt][3];
        }
        rs0 += __shfl_xor_sync(0xffffffffu, rs0, 1);
        rs0 += __shfl_xor_sync(0xffffffffu, rs0, 2);
        rs1 += __shfl_xor_sync(0xffffffffu, rs1, 1);
        rs1 += __shfl_xor_sync(0xffffffffu, rs1, 2);
        l0 = l0 * al0 + rs0;
        l1 = l1 * al1 + rs1;
#pragma unroll
        for (int nt = 0; nt < 16; nt++) {
            O[nt][0] *= al0;
            O[nt][1] *= al0;
            O[nt][2] *= al1;
            O[nt][3] *= al1;
        }

        // O += P V  (P packed to fp16 A-fragments directly from registers)
#pragma unroll
        for (int kt = 0; kt < 4; kt++) {
            uint32_t a[4];
            a[0] = packh2(Sa[2 * kt][0], Sa[2 * kt][1]);
            a[1] = packh2(Sa[2 * kt][2], Sa[2 * kt][3]);
            a[2] = packh2(Sa[2 * kt + 1][0], Sa[2 * kt + 1][1]);
            a[3] = packh2(Sa[2 * kt + 1][2], Sa[2 * kt + 1][3]);
#pragma unroll
            for (int bt = 0; bt < 8; bt++) {
                uint32_t b[4];
                ldsm4t(b, vB + ((kt * 16 + v_krow) * FSV + bt * 16 + v_dch) * 2);
                mma16816(O[2 * bt], a, b[0], b[1]);
                mma16816(O[2 * bt + 1], a, b[2], b[3]);
            }
        }
    }

    // normalize + write fp16 to g_attnH [M, D_MODEL], columns h*128+d
    float il0 = 1.f / l0, il1 = 1.f / l1;
    const int hh = bh & (NHEADS - 1);
    const int bb = bh >> 4;
    __half* base0 = g_attnH + ((size_t)(bb * S + q0)) * D_MODEL + hh * DK;
    __half* base1 = base0 + (size_t)8 * D_MODEL;
#pragma unroll
    for (int nt = 0; nt < 16; nt++) {
        int d = nt * 8 + lc * 2;
        *reinterpret_cast<uint32_t*>(base0 + d) = packh2(O[nt][0] * il0, O[nt][1] * il0);
        *reinterpret_cast<uint32_t*>(base1 + d) = packh2(O[nt][2] * il1, O[nt][3] * il1);
    }
}

// ---------------- launch ----------------
extern "C" void kernel_launch(void* const* d_in, const int* in_sizes, int n_in,
                              void* d_out, int out_size) {
    const float* x = (const float*)d_in[0];
    const float* Wq = (const float*)d_in[1];
    const float* Wk = (const float*)d_in[2];
    const float* Wv = (const float*)d_in[3];
    const float* Wo = (const float*)d_in[4];
    const int* pos = (const int*)d_in[5];

    const int S = in_sizes[5];
    const int M = in_sizes[0] / D_MODEL;
    const int B = M / S;

    cudaFuncSetAttribute(gemm_f16_kernel, cudaFuncAttributeMaxDynamicSharedMemorySize, G_SMEM);
    cudaFuncSetAttribute(fa_kernel, cudaFuncAttributeMaxDynamicSharedMemorySize, FA_SMEM);

    // 1) RoPE tables + fp16 conversions
    rope_table_kernel<<<(S * (DK / 2) + 255) / 256, 256>>>(pos, S);
    convert_x_kernel<<<(M * D_MODEL / 4 + 255) / 256, 256>>>(x, M * D_MODEL);
    transpose_w_kernel<<<dim3(64, 64, 4), dim3(32, 8)>>>(Wq, Wk, Wv, Wo);

    // 2) fused QKV projection + RoPE (z selects Q/K/V)
    gemm_f16_kernel<<<dim3(D_MODEL / 256, M / 128, 3), 256, G_SMEM>>>(nullptr, M, S, -1);

    // 3) causal flash attention
    fa_kernel<<<dim3(S / 128, B * NHEADS), 256, FA_SMEM>>>(S);

    // 4) output projection
    gemm_f16_kernel<<<dim3(D_MODEL / 256, M / 128, 1), 256, G_SMEM>>>((float*)d_out, M, S, 3);
}

// round 8
// speedup vs baseline: 1.0709x; 1.0709x over previous
#include <cuda_runtime.h>
#include <cuda_fp16.h>
#include <cstdint>
#include <math.h>

#define D_MODEL 2048
#define NHEADS 16
#define DK 128
#define MAX_S 2048
#define MAX_M 4096
#define W_ELEMS ((size_t)D_MODEL * D_MODEL)

// ---------------- scratch (static device globals; no allocation) ----------------
__device__ __half g_Wt[4 * W_ELEMS];                 // [4][f][d] transposed fp16 weights (q,k,v,o)
__device__ __half g_xh[(size_t)MAX_M * D_MODEL];     // fp16 copy of x
__device__ __half g_Qh[(size_t)MAX_M * D_MODEL];     // [B,H,S,DK] (scale folded)
__device__ __half g_Kh[(size_t)MAX_M * D_MODEL];
__device__ __half g_Vh[(size_t)MAX_M * D_MODEL];
__device__ __half g_attnH[(size_t)MAX_M * D_MODEL];  // [M, D_MODEL]
__device__ float g_cosT[MAX_S * (DK / 2)];
__device__ float g_sinT[MAX_S * (DK / 2)];

// ---------------- asm helpers ----------------
__device__ __forceinline__ void ldsm4(uint32_t* r, uint32_t addr) {
    asm volatile("ldmatrix.sync.aligned.m8n8.x4.shared.b16 {%0,%1,%2,%3}, [%4];"
                 : "=r"(r[0]), "=r"(r[1]), "=r"(r[2]), "=r"(r[3]) : "r"(addr));
}
__device__ __forceinline__ void ldsm4t(uint32_t* r, uint32_t addr) {
    asm volatile("ldmatrix.sync.aligned.m8n8.x4.trans.shared.b16 {%0,%1,%2,%3}, [%4];"
                 : "=r"(r[0]), "=r"(r[1]), "=r"(r[2]), "=r"(r[3]) : "r"(addr));
}
__device__ __forceinline__ void mma16816(float* d, const uint32_t* a, uint32_t b0, uint32_t b1) {
    asm volatile(
        "mma.sync.aligned.m16n8k16.row.col.f32.f16.f16.f32 "
        "{%0,%1,%2,%3}, {%4,%5,%6,%7}, {%8,%9}, {%0,%1,%2,%3};"
        : "+f"(d[0]), "+f"(d[1]), "+f"(d[2]), "+f"(d[3])
        : "r"(a[0]), "r"(a[1]), "r"(a[2]), "r"(a[3]), "r"(b0), "r"(b1));
}
__device__ __forceinline__ void cp16(uint32_t saddr, const void* gptr) {
    asm volatile("cp.async.cg.shared.global [%0], [%1], 16;" :: "r"(saddr), "l"(gptr));
}
__device__ __forceinline__ void cp_commit() { asm volatile("cp.async.commit_group;"); }
#define CP_WAIT(N) asm volatile("cp.async.wait_group %0;" :: "n"(N))
__device__ __forceinline__ uint32_t packh2(float a, float b) {
    __half2 h = __floats2half2_rn(a, b);
    return *reinterpret_cast<uint32_t*>(&h);
}

// ---------------- RoPE table ----------------
__global__ void rope_table_kernel(const int* __restrict__ pos, int S) {
    int idx = blockIdx.x * blockDim.x + threadIdx.x;
    if (idx >= S * (DK / 2)) return;
    int s = idx / (DK / 2);
    int i = idx % (DK / 2);
    float invf = (float)pow(10000.0, -(double)(2 * i) / (double)DK);
    float ang = (float)pos[s] * invf;
    g_cosT[idx] = cosf(ang);
    g_sinT[idx] = sinf(ang);
}

// ---------------- converters ----------------
__global__ void convert_x_kernel(const float* __restrict__ x, int n) {
    int i = (blockIdx.x * blockDim.x + threadIdx.x) * 4;
    if (i >= n) return;
    float4 v = *reinterpret_cast<const float4*>(x + i);
    uint2 u = {packh2(v.x, v.y), packh2(v.z, v.w)};
    *reinterpret_cast<uint2*>(&g_xh[i]) = u;
}

__global__ void transpose_w_kernel(const float* __restrict__ Wq, const float* __restrict__ Wk,
                                   const float* __restrict__ Wv, const float* __restrict__ Wo) {
    __shared__ float t[32][33];
    const int z = blockIdx.z;
    const float* W = (z == 0) ? Wq : (z == 1) ? Wk : (z == 2) ? Wv : Wo;
    __half* dst = g_Wt + (size_t)z * W_ELEMS;
    int x0 = blockIdx.x * 32, y0 = blockIdx.y * 32;
    int tx = threadIdx.x, ty = threadIdx.y;
#pragma unroll
    for (int i = 0; i < 4; i++)
        t[ty + i * 8][tx] = W[(size_t)(y0 + ty + i * 8) * D_MODEL + x0 + tx];
    __syncthreads();
#pragma unroll
    for (int i = 0; i < 4; i++)
        dst[(size_t)(x0 + ty + i * 8) * D_MODEL + y0 + tx] = __float2half(t[tx][ty + i * 8]);
}

// ---------------- GEMM: 512 threads, 128x256 CTA tile, 32x64 warp tiles ----------
// R5's proven per-warp shape (32x64, 128 regs, 4 warps/SMSP) with a fatter CTA:
// halves cp.async store B/MAC (0.035 -> 0.028) and cuts B-tile L2 traffic 25%.
#define SA 72                      // halves per smem row (64 data + 8 pad); 144B stride
#define GA_STG (128 * SA * 2)      // A stage bytes (18432)
#define GB_STG (256 * SA * 2)      // B stage bytes (36864)
#define G_STG (GA_STG + GB_STG)    // 55296
#define G_SMEM (3 * G_STG)         // 165888

__global__ __launch_bounds__(512, 1) void gemm_f16_kernel(float* __restrict__ outF, int M,
                                                          int S, int mode_in) {
    extern __shared__ __align__(16) unsigned char smraw[];
    uint32_t sm = (uint32_t)__cvta_generic_to_shared(smraw);

    const int mode = (mode_in < 0) ? (int)blockIdx.z : mode_in;
    const __half* Ag = (mode_in < 0) ? g_xh : g_attnH;
    const __half* Bg = g_Wt + (size_t)mode * W_ELEMS;  // [n][k] fp16
    const int bm = blockIdx.y * 128;
    const int bn = blockIdx.x * 256;
    const int tid = threadIdx.x;
    const int lane = tid & 31, wid = tid >> 5;
    const int wm = wid & 3, wn = wid >> 2;  // 4 warps along M (32 rows), 4 along N (64 cols)
    const int lr = lane >> 2, lc = lane & 3;

    // ldmatrix lane address components
    const int a_row = (lane & 7) + ((lane >> 3) & 1) * 8;
    const int a_ch = (lane >> 4) * 8;
    const int aoff0 = ((wm * 32 + a_row) * SA + a_ch) * 2;
    const int aoff1 = ((wm * 32 + 16 + a_row) * SA + a_ch) * 2;
    const int b_row = (lane >> 4) * 8 + (lane & 7);
    const int b_k = ((lane >> 3) & 1) * 8;
    const int boff = ((wn * 64 + b_row) * SA + b_k) * 2;

    float acc[2][8][4];
#pragma unroll
    for (int i = 0; i < 2; i++)
#pragma unroll
        for (int j = 0; j < 8; j++)
#pragma unroll
            for (int k = 0; k < 4; k++) acc[i][j][k] = 0.f;

    auto prefetch = [&](int stage, int kt) {
        uint32_t aB = sm + stage * G_STG;
        uint32_t bB = aB + GA_STG;
        const __half* Ap = Ag + (size_t)bm * D_MODEL + kt * 64;
        const __half* Bp = Bg + (size_t)bn * D_MODEL + kt * 64;
#pragma unroll
        for (int i = 0; i < 2; i++) {  // A: 128 rows x 8 chunks of 16B = 1024 chunks
            int idx = tid + i * 512;
            int r = idx >> 3, c = (idx & 7) * 8;
            cp16(aB + (r * SA + c) * 2, Ap + (size_t)r * D_MODEL + c);
        }
#pragma unroll
        for (int i = 0; i < 4; i++) {  // B: 256 rows x 8 chunks = 2048 chunks
            int idx = tid + i * 512;
            int r = idx >> 3, c = (idx & 7) * 8;
            cp16(bB + (r * SA + c) * 2, Bp + (size_t)r * D_MODEL + c);
        }
    };

    prefetch(0, 0);
    cp_commit();
    prefetch(1, 1);
    cp_commit();

    for (int kt = 0; kt < 32; kt++) {
        CP_WAIT(1);
        __syncthreads();
        if (kt + 2 < 32) prefetch((kt + 2) % 3, kt + 2);
        cp_commit();

        uint32_t aB = sm + (kt % 3) * G_STG;
        uint32_t bB = aB + GA_STG;
#pragma unroll
        for (int kk = 0; kk < 4; kk++) {
            uint32_t a0[4], a1[4];
            ldsm4(a0, aB + aoff0 + kk * 32);
            ldsm4(a1, aB + aoff1 + kk * 32);
#pragma unroll
            for (int bt = 0; bt < 4; bt++) {
                uint32_t b[4];
                ldsm4(b, bB + boff + bt * 16 * SA * 2 + kk * 32);
                mma16816(acc[0][2 * bt], a0, b[0], b[1]);
                mma16816(acc[1][2 * bt], a1, b[0], b[1]);
                mma16816(acc[0][2 * bt + 1], a0, b[2], b[3]);
                mma16816(acc[1][2 * bt + 1], a1, b[2], b[3]);
            }
        }
    }

    // epilogue: c0,c1 = columns (2lc, 2lc+1) -> RoPE pair
#pragma unroll
    for (int mt = 0; mt < 2; mt++) {
#pragma unroll
        for (int nt = 0; nt < 8; nt++) {
#pragma unroll
            for (int half = 0; half < 2; half++) {
                int m = bm + wm * 32 + mt * 16 + lr + half * 8;
                int f = bn + wn * 64 + nt * 8 + lc * 2;
                float c0 = acc[mt][nt][half * 2];
                float c1 = acc[mt][nt][half * 2 + 1];
                if (mode == 3) {
                    *reinterpret_cast<float2*>(outF + (size_t)m * D_MODEL + f) =
                        make_float2(c0, c1);
                } else {
                    int b = m / S, s = m - b * S;
                    int h = f >> 7, d = f & (DK - 1);
                    float o0 = c0, o1 = c1;
                    if (mode < 2) {
                        int i = d >> 1;
                        float cs = g_cosT[s * (DK / 2) + i];
                        float sn = g_sinT[s * (DK / 2) + i];
                        o0 = c0 * cs - c1 * sn;
                        o1 = c0 * sn + c1 * cs;
                        if (mode == 0) {  // fold 1/sqrt(DK) into Q
                            o0 *= 0.08838834764831845f;
                            o1 *= 0.08838834764831845f;
                        }
                    }
                    __half* dst = ((mode == 0) ? g_Qh : (mode == 1) ? g_Kh : g_Vh) +
                                  ((size_t)(b * NHEADS + h) * S + s) * DK + d;
                    *reinterpret_cast<uint32_t*>(dst) = packh2(o0, o1);
                }
            }
        }
    }
}

// ---------------- Flash attention: Br=128, Bc=64, fp16, reg-resident P ----------------
#define FSV 136                      // halves per smem row (128 data + 8 pad); 272B
#define Q_HALVES (128 * FSV)
#define KV_STAGE_H (64 * FSV)
#define FA_SMEM ((Q_HALVES + 6 * KV_STAGE_H) * 2)  // 139264

__global__ __launch_bounds__(256, 1) void fa_kernel(int S) {
    extern __shared__ __align__(16) unsigned char smraw[];
    uint32_t sm = (uint32_t)__cvta_generic_to_shared(smraw);

    const int bh = blockIdx.y;
    const int qtile = blockIdx.x;
    const int qbase = qtile * 128;
    const __half* Qp = g_Qh + (size_t)bh * S * DK;
    const __half* Kp = g_Kh + (size_t)bh * S * DK;
    const __half* Vp = g_Vh + (size_t)bh * S * DK;

    const int tid = threadIdx.x, lane = tid & 31, wid = tid >> 5;
    const int lr = lane >> 2, lc = lane & 3;

    // Q tile -> smem via cp.async (group 0)
#pragma unroll
    for (int i = 0; i < 8; i++) {
        int idx = tid + i * 256;
        int r = idx >> 4, c = (idx & 15) * 8;
        cp16(sm + (r * FSV + c) * 2, Qp + (size_t)(qbase + r) * DK + c);
    }
    cp_commit();

    auto prefetchKV = [&](int j, int stage) {
        uint32_t kB = sm + (Q_HALVES + stage * KV_STAGE_H) * 2;
        uint32_t vB = sm + (Q_HALVES + (3 + stage) * KV_STAGE_H) * 2;
        const __half* Kt = Kp + (size_t)(j * 64) * DK;
        const __half* Vt = Vp + (size_t)(j * 64) * DK;
#pragma unroll
        for (int i = 0; i < 4; i++) {
            int idx = tid + i * 256;
            int r = idx >> 4, c = (idx & 15) * 8;
            cp16(kB + (r * FSV + c) * 2, Kt + (size_t)r * DK + c);
            cp16(vB + (r * FSV + c) * 2, Vt + (size_t)r * DK + c);
        }
    };

    prefetchKV(0, 0);
    cp_commit();
    prefetchKV(1, 1);
    cp_commit();

    CP_WAIT(2);  // Q resident
    __syncthreads();

    // preload Q fragments (reused across all kv tiles)
    uint32_t Qf[8][4];
    {
        int r = wid * 16 + (lane & 7) + ((lane >> 3) & 1) * 8;
        int ch = (lane >> 4) * 8;
#pragma unroll
        for (int kk = 0; kk < 8; kk++) ldsm4(Qf[kk], sm + (r * FSV + ch + kk * 16) * 2);
    }

    float O[16][4];
#pragma unroll
    for (int i = 0; i < 16; i++)
#pragma unroll
        for (int j = 0; j < 4; j++) O[i][j] = 0.f;
    float m0 = -INFINITY, m1 = -INFINITY, l0 = 0.f, l1 = 0.f;

    const int nkv = 2 * qtile + 2;
    const int q0 = qbase + wid * 16 + lr;

    // ldmatrix lane components
    const int kb_row = (lane >> 4) * 8 + (lane & 7);        // K: key row
    const int kb_k = ((lane >> 3) & 1) * 8;                 // K: d offset
    const int v_krow = (lane & 7) + ((lane >> 3) & 1) * 8;  // V: key row within 16
    const int v_dch = (lane >> 4) * 8;                      // V: d chunk offset

    for (int j = 0; j < nkv; j++) {
        CP_WAIT(1);
        __syncthreads();
        if (j + 2 < nkv) prefetchKV(j + 2, (j + 2) % 3);
        cp_commit();

        const int stage = j % 3;
        const uint32_t kB = sm + (Q_HALVES + stage * KV_STAGE_H) * 2;
        const uint32_t vB = sm + (Q_HALVES + (3 + stage) * KV_STAGE_H) * 2;
        const int kv0 = j * 64;

        // S = Q K^T
        float Sa[8][4];
#pragma unroll
        for (int i = 0; i < 8; i++)
#pragma unroll
            for (int t = 0; t < 4; t++) Sa[i][t] = 0.f;
#pragma unroll
        for (int kk = 0; kk < 8; kk++) {
#pragma unroll
            for (int bt = 0; bt < 4; bt++) {
                uint32_t b[4];
                ldsm4(b, kB + ((bt * 16 + kb_row) * FSV + kb_k + kk * 16) * 2);
                mma16816(Sa[2 * bt], Qf[kk], b[0], b[1]);
                mma16816(Sa[2 * bt + 1], Qf[kk], b[2], b[3]);
            }
        }

        // causal mask (only last two kv tiles overlap the diagonal)
        if (j >= nkv - 2) {
#pragma unroll
            for (int nt = 0; nt < 8; nt++) {
                int key = kv0 + nt * 8 + lc * 2;
                if (key > q0) Sa[nt][0] = -INFINITY;
                if (key + 1 > q0) Sa[nt][1] = -INFINITY;
                if (key > q0 + 8) Sa[nt][2] = -INFINITY;
                if (key + 1 > q0 + 8) Sa[nt][3] = -INFINITY;
            }
        }

        // online softmax (fp32)
        float mx0 = -INFINITY, mx1 = -INFINITY;
#pragma unroll
        for (int nt = 0; nt < 8; nt++) {
            mx0 = fmaxf(mx0, fmaxf(Sa[nt][0], Sa[nt][1]));
            mx1 = fmaxf(mx1, fmaxf(Sa[nt][2], Sa[nt][3]));
        }
        mx0 = fmaxf(mx0, __shfl_xor_sync(0xffffffffu, mx0, 1));
        mx0 = fmaxf(mx0, __shfl_xor_sync(0xffffffffu, mx0, 2));
        mx1 = fmaxf(mx1, __shfl_xor_sync(0xffffffffu, mx1, 1));
        mx1 = fmaxf(mx1, __shfl_xor_sync(0xffffffffu, mx1, 2));
        float mn0 = fmaxf(m0, mx0), mn1 = fmaxf(m1, mx1);
        float al0 = __expf(m0 - mn0), al1 = __expf(m1 - mn1);
        m0 = mn0;
        m1 = mn1;
        float rs0 = 0.f, rs1 = 0.f;
#pragma unroll
        for (int nt = 0; nt < 8; nt++) {
            Sa[nt][0] = __expf(Sa[nt][0] - mn0);
            Sa[nt][1] = __expf(Sa[nt][1] - mn0);
            Sa[nt][2] = __expf(Sa[nt][2] - mn1);
            Sa[nt][3] = __expf(Sa[nt][3] - mn1);
            rs0 += Sa[nt][0] + Sa[nt][1];
            rs1 += Sa[nt][2] + Sa[nt][3];
        }
        rs0 += __shfl_xor_sync(0xffffffffu, rs0, 1);
        rs0 += __shfl_xor_sync(0xffffffffu, rs0, 2);
        rs1 += __shfl_xor_sync(0xffffffffu, rs1, 1);
        rs1 += __shfl_xor_sync(0xffffffffu, rs1, 2);
        l0 = l0 * al0 + rs0;
        l1 = l1 * al1 + rs1;
#pragma unroll
        for (int nt = 0; nt < 16; nt++) {
            O[nt][0] *= al0;
            O[nt][1] *= al0;
            O[nt][2] *= al1;
            O[nt][3] *= al1;
        }

        // O += P V  (P packed to fp16 A-fragments directly from registers)
#pragma unroll
        for (int kt = 0; kt < 4; kt++) {
            uint32_t a[4];
            a[0] = packh2(Sa[2 * kt][0], Sa[2 * kt][1]);
            a[1] = packh2(Sa[2 * kt][2], Sa[2 * kt][3]);
            a[2] = packh2(Sa[2 * kt + 1][0], Sa[2 * kt + 1][1]);
            a[3] = packh2(Sa[2 * kt + 1][2], Sa[2 * kt + 1][3]);
#pragma unroll
            for (int bt = 0; bt < 8; bt++) {
                uint32_t b[4];
                ldsm4t(b, vB + ((kt * 16 + v_krow) * FSV + bt * 16 + v_dch) * 2);
                mma16816(O[2 * bt], a, b[0], b[1]);
                mma16816(O[2 * bt + 1], a, b[2], b[3]);
            }
        }
    }

    // normalize + write fp16 to g_attnH [M, D_MODEL], columns h*128+d
    float il0 = 1.f / l0, il1 = 1.f / l1;
    const int hh = bh & (NHEADS - 1);
    const int bb = bh >> 4;
    __half* base0 = g_attnH + ((size_t)(bb * S + q0)) * D_MODEL + hh * DK;
    __half* base1 = base0 + (size_t)8 * D_MODEL;
#pragma unroll
    for (int nt = 0; nt < 16; nt++) {
        int d = nt * 8 + lc * 2;
        *reinterpret_cast<uint32_t*>(base0 + d) = packh2(O[nt][0] * il0, O[nt][1] * il0);
        *reinterpret_cast<uint32_t*>(base1 + d) = packh2(O[nt][2] * il1, O[nt][3] * il1);
    }
}

// ---------------- launch ----------------
extern "C" void kernel_launch(void* const* d_in, const int* in_sizes, int n_in,
                              void* d_out, int out_size) {
    const float* x = (const float*)d_in[0];
    const float* Wq = (const float*)d_in[1];
    const float* Wk = (const float*)d_in[2];
    const float* Wv = (const float*)d_in[3];
    const float* Wo = (const float*)d_in[4];
    const int* pos = (const int*)d_in[5];

    const int S = in_sizes[5];
    const int M = in_sizes[0] / D_MODEL;
    const int B = M / S;

    cudaFuncSetAttribute(gemm_f16_kernel, cudaFuncAttributeMaxDynamicSharedMemorySize, G_SMEM);
    cudaFuncSetAttribute(fa_kernel, cudaFuncAttributeMaxDynamicSharedMemorySize, FA_SMEM);

    // 1) RoPE tables + fp16 conversions
    rope_table_kernel<<<(S * (DK / 2) + 255) / 256, 256>>>(pos, S);
    convert_x_kernel<<<(M * D_MODEL / 4 + 255) / 256, 256>>>(x, M * D_MODEL);
    transpose_w_kernel<<<dim3(64, 64, 4), dim3(32, 8)>>>(Wq, Wk, Wv, Wo);

    // 2) fused QKV projection + RoPE (z selects Q/K/V)
    gemm_f16_kernel<<<dim3(D_MODEL / 256, M / 128, 3), 512, G_SMEM>>>(nullptr, M, S, -1);

    // 3) causal flash attention
    fa_kernel<<<dim3(S / 128, B * NHEADS), 256, FA_SMEM>>>(S);

    // 4) output projection
    gemm_f16_kernel<<<dim3(D_MODEL / 256, M / 128, 1), 512, G_SMEM>>>((float*)d_out, M, S, 3);
}

// round 9
// speedup vs baseline: 1.1384x; 1.0630x over previous
#include <cuda_runtime.h>
#include <cuda_fp16.h>
#include <cstdint>
#include <math.h>

#define D_MODEL 2048
#define NHEADS 16
#define DK 128
#define MAX_S 2048
#define MAX_M 4096
#define W_ELEMS ((size_t)D_MODEL * D_MODEL)

// ---------------- scratch (static device globals; no allocation) ----------------
__device__ __half g_Wt[4 * W_ELEMS];                 // [4][f][d] transposed fp16 weights (q,k,v,o)
__device__ __half g_xh[(size_t)MAX_M * D_MODEL];     // fp16 copy of x
__device__ __half g_Qh[(size_t)MAX_M * D_MODEL];     // [B,H,S,DK] (scale folded)
__device__ __half g_Kh[(size_t)MAX_M * D_MODEL];
__device__ __half g_Vh[(size_t)MAX_M * D_MODEL];
__device__ __half g_attnH[(size_t)MAX_M * D_MODEL];  // [M, D_MODEL]
__device__ float g_cosT[MAX_S * (DK / 2)];
__device__ float g_sinT[MAX_S * (DK / 2)];

// ---------------- asm helpers ----------------
__device__ __forceinline__ void ldsm4(uint32_t* r, uint32_t addr) {
    asm volatile("ldmatrix.sync.aligned.m8n8.x4.shared.b16 {%0,%1,%2,%3}, [%4];"
                 : "=r"(r[0]), "=r"(r[1]), "=r"(r[2]), "=r"(r[3]) : "r"(addr));
}
__device__ __forceinline__ void ldsm4t(uint32_t* r, uint32_t addr) {
    asm volatile("ldmatrix.sync.aligned.m8n8.x4.trans.shared.b16 {%0,%1,%2,%3}, [%4];"
                 : "=r"(r[0]), "=r"(r[1]), "=r"(r[2]), "=r"(r[3]) : "r"(addr));
}
__device__ __forceinline__ void mma16816(float* d, const uint32_t* a, uint32_t b0, uint32_t b1) {
    asm volatile(
        "mma.sync.aligned.m16n8k16.row.col.f32.f16.f16.f32 "
        "{%0,%1,%2,%3}, {%4,%5,%6,%7}, {%8,%9}, {%0,%1,%2,%3};"
        : "+f"(d[0]), "+f"(d[1]), "+f"(d[2]), "+f"(d[3])
        : "r"(a[0]), "r"(a[1]), "r"(a[2]), "r"(a[3]), "r"(b0), "r"(b1));
}
__device__ __forceinline__ void cp16(uint32_t saddr, const void* gptr) {
    asm volatile("cp.async.cg.shared.global [%0], [%1], 16;" :: "r"(saddr), "l"(gptr));
}
__device__ __forceinline__ void cp_commit() { asm volatile("cp.async.commit_group;"); }
#define CP_WAIT(N) asm volatile("cp.async.wait_group %0;" :: "n"(N))
__device__ __forceinline__ uint32_t packh2(float a, float b) {
    __half2 h = __floats2half2_rn(a, b);
    return *reinterpret_cast<uint32_t*>(&h);
}

// ---------------- RoPE table ----------------
__global__ void rope_table_kernel(const int* __restrict__ pos, int S) {
    int idx = blockIdx.x * blockDim.x + threadIdx.x;
    if (idx >= S * (DK / 2)) return;
    int s = idx / (DK / 2);
    int i = idx % (DK / 2);
    float invf = (float)pow(10000.0, -(double)(2 * i) / (double)DK);
    float ang = (float)pos[s] * invf;
    g_cosT[idx] = cosf(ang);
    g_sinT[idx] = sinf(ang);
}

// ---------------- converters ----------------
__global__ void convert_x_kernel(const float* __restrict__ x, int n) {
    int i = (blockIdx.x * blockDim.x + threadIdx.x) * 4;
    if (i >= n) return;
    float4 v = *reinterpret_cast<const float4*>(x + i);
    uint2 u = {packh2(v.x, v.y), packh2(v.z, v.w)};
    *reinterpret_cast<uint2*>(&g_xh[i]) = u;
}

__global__ void transpose_w_kernel(const float* __restrict__ Wq, const float* __restrict__ Wk,
                                   const float* __restrict__ Wv, const float* __restrict__ Wo) {
    __shared__ float t[32][33];
    const int z = blockIdx.z;
    const float* W = (z == 0) ? Wq : (z == 1) ? Wk : (z == 2) ? Wv : Wo;
    __half* dst = g_Wt + (size_t)z * W_ELEMS;
    int x0 = blockIdx.x * 32, y0 = blockIdx.y * 32;
    int tx = threadIdx.x, ty = threadIdx.y;
#pragma unroll
    for (int i = 0; i < 4; i++)
        t[ty + i * 8][tx] = W[(size_t)(y0 + ty + i * 8) * D_MODEL + x0 + tx];
    __syncthreads();
#pragma unroll
    for (int i = 0; i < 4; i++)
        dst[(size_t)(x0 + ty + i * 8) * D_MODEL + y0 + tx] = __float2half(t[tx][ty + i * 8]);
}

// ---------------- GEMM: 128x128 CTA tile, fp16 mma, 3-stage cp.async ----------------
// R5 backbone (2 CTAs/SM, 4 warps/SMSP — the proven best). R8 delta: all 8
// A-fragment ldmatrix per k-tile hoisted ahead of the kk loop so the kk body
// is a pure b-ldsm -> mma stream (A-load latency overlapped with prior mma).
#define SA 72                       // halves per smem row (64 data + 8 pad); 144B stride
#define G_STAGE_B (128 * SA * 2)    // bytes per matrix per stage (18432)
#define G_SMEM (3 * 2 * G_STAGE_B)  // 110592

__global__ __launch_bounds__(256, 2) void gemm_f16_kernel(float* __restrict__ outF, int M,
                                                          int S, int mode_in) {
    extern __shared__ __align__(16) unsigned char smraw[];
    uint32_t sm = (uint32_t)__cvta_generic_to_shared(smraw);

    const int mode = (mode_in < 0) ? (int)blockIdx.z : mode_in;
    const __half* Ag = (mode_in < 0) ? g_xh : g_attnH;
    const __half* Bg = g_Wt + (size_t)mode * W_ELEMS;  // [n][k] fp16
    const int bm = blockIdx.y * 128;
    const int bn = blockIdx.x * 128;
    const int tid = threadIdx.x;
    const int lane = tid & 31, wid = tid >> 5;
    const int wm = wid & 3, wn = wid >> 2;
    const int lr = lane >> 2, lc = lane & 3;

    // ldmatrix lane address components
    const int a_row = (lane & 7) + ((lane >> 3) & 1) * 8;
    const int a_ch = (lane >> 4) * 8;
    const int aoff0 = ((wm * 32 + a_row) * SA + a_ch) * 2;
    const int aoff1 = ((wm * 32 + 16 + a_row) * SA + a_ch) * 2;
    const int b_row = (lane >> 4) * 8 + (lane & 7);
    const int b_k = ((lane >> 3) & 1) * 8;
    const int boff = ((wn * 64 + b_row) * SA + b_k) * 2;

    float acc[2][8][4];
#pragma unroll
    for (int i = 0; i < 2; i++)
#pragma unroll
        for (int j = 0; j < 8; j++)
#pragma unroll
            for (int k = 0; k < 4; k++) acc[i][j][k] = 0.f;

    auto prefetch = [&](int stage, int kt) {
        uint32_t aB = sm + stage * 2 * G_STAGE_B;
        uint32_t bB = aB + G_STAGE_B;
        const __half* Ap = Ag + (size_t)bm * D_MODEL + kt * 64;
        const __half* Bp = Bg + (size_t)bn * D_MODEL + kt * 64;
#pragma unroll
        for (int i = 0; i < 4; i++) {
            int idx = tid + i * 256;
            int r = idx >> 3, c = (idx & 7) * 8;
            cp16(aB + (r * SA + c) * 2, Ap + (size_t)r * D_MODEL + c);
            cp16(bB + (r * SA + c) * 2, Bp + (size_t)r * D_MODEL + c);
        }
    };

    prefetch(0, 0);
    cp_commit();
    prefetch(1, 1);
    cp_commit();

    for (int kt = 0; kt < 32; kt++) {
        CP_WAIT(1);
        __syncthreads();
        if (kt + 2 < 32) prefetch((kt + 2) % 3, kt + 2);
        cp_commit();

        uint32_t aB = sm + (kt % 3) * 2 * G_STAGE_B;
        uint32_t bB = aB + G_STAGE_B;

        // hoisted A fragments for the whole k-tile (32 regs)
        uint32_t aF[4][2][4];
#pragma unroll
        for (int kk = 0; kk < 4; kk++) {
            ldsm4(aF[kk][0], aB + aoff0 + kk * 32);
            ldsm4(aF[kk][1], aB + aoff1 + kk * 32);
        }
#pragma unroll
        for (int kk = 0; kk < 4; kk++) {
#pragma unroll
            for (int bt = 0; bt < 4; bt++) {
                uint32_t b[4];
                ldsm4(b, bB + boff + bt * 16 * SA * 2 + kk * 32);
                mma16816(acc[0][2 * bt], aF[kk][0], b[0], b[1]);
                mma16816(acc[1][2 * bt], aF[kk][1], b[0], b[1]);
                mma16816(acc[0][2 * bt + 1], aF[kk][0], b[2], b[3]);
                mma16816(acc[1][2 * bt + 1], aF[kk][1], b[2], b[3]);
            }
        }
    }

    // epilogue: c0,c1 = columns (2lc, 2lc+1) -> RoPE pair
#pragma unroll
    for (int mt = 0; mt < 2; mt++) {
#pragma unroll
        for (int nt = 0; nt < 8; nt++) {
#pragma unroll
            for (int half = 0; half < 2; half++) {
                int m = bm + wm * 32 + mt * 16 + lr + half * 8;
                int f = bn + wn * 64 + nt * 8 + lc * 2;
                float c0 = acc[mt][nt][half * 2];
                float c1 = acc[mt][nt][half * 2 + 1];
                if (mode == 3) {
                    *reinterpret_cast<float2*>(outF + (size_t)m * D_MODEL + f) =
                        make_float2(c0, c1);
                } else {
                    int b = m / S, s = m - b * S;
                    int h = f >> 7, d = f & (DK - 1);
                    float o0 = c0, o1 = c1;
                    if (mode < 2) {
                        int i = d >> 1;
                        float cs = g_cosT[s * (DK / 2) + i];
                        float sn = g_sinT[s * (DK / 2) + i];
                        o0 = c0 * cs - c1 * sn;
                        o1 = c0 * sn + c1 * cs;
                        if (mode == 0) {  // fold 1/sqrt(DK) into Q
                            o0 *= 0.08838834764831845f;
                            o1 *= 0.08838834764831845f;
                        }
                    }
                    __half* dst = ((mode == 0) ? g_Qh : (mode == 1) ? g_Kh : g_Vh) +
                                  ((size_t)(b * NHEADS + h) * S + s) * DK + d;
                    *reinterpret_cast<uint32_t*>(dst) = packh2(o0, o1);
                }
            }
        }
    }
}

// ---------------- Flash attention: Br=128, Bc=64, fp16, reg-resident P ----------------
#define FSV 136                      // halves per smem row (128 data + 8 pad); 272B
#define Q_HALVES (128 * FSV)
#define KV_STAGE_H (64 * FSV)
#define FA_SMEM ((Q_HALVES + 6 * KV_STAGE_H) * 2)  // 139264

__global__ __launch_bounds__(256, 1) void fa_kernel(int S) {
    extern __shared__ __align__(16) unsigned char smraw[];
    uint32_t sm = (uint32_t)__cvta_generic_to_shared(smraw);

    const int bh = blockIdx.y;
    // longest-first scheduling: high qtile (most kv-iters) launches first
    const int qtile = gridDim.x - 1 - blockIdx.x;
    const int qbase = qtile * 128;
    const __half* Qp = g_Qh + (size_t)bh * S * DK;
    const __half* Kp = g_Kh + (size_t)bh * S * DK;
    const __half* Vp = g_Vh + (size_t)bh * S * DK;

    const int tid = threadIdx.x, lane = tid & 31, wid = tid >> 5;
    const int lr = lane >> 2, lc = lane & 3;

    // Q tile -> smem via cp.async (group 0)
#pragma unroll
    for (int i = 0; i < 8; i++) {
        int idx = tid + i * 256;
        int r = idx >> 4, c = (idx & 15) * 8;
        cp16(sm + (r * FSV + c) * 2, Qp + (size_t)(qbase + r) * DK + c);
    }
    cp_commit();

    auto prefetchKV = [&](int j, int stage) {
        uint32_t kB = sm + (Q_HALVES + stage * KV_STAGE_H) * 2;
        uint32_t vB = sm + (Q_HALVES + (3 + stage) * KV_STAGE_H) * 2;
        const __half* Kt = Kp + (size_t)(j * 64) * DK;
        const __half* Vt = Vp + (size_t)(j * 64) * DK;
#pragma unroll
        for (int i = 0; i < 4; i++) {
            int idx = tid + i * 256;
            int r = idx >> 4, c = (idx & 15) * 8;
            cp16(kB + (r * FSV + c) * 2, Kt + (size_t)r * DK + c);
            cp16(vB + (r * FSV + c) * 2, Vt + (size_t)r * DK + c);
        }
    };

    prefetchKV(0, 0);
    cp_commit();
    prefetchKV(1, 1);
    cp_commit();

    CP_WAIT(2);  // Q resident
    __syncthreads();

    // preload Q fragments (reused across all kv tiles)
    uint32_t Qf[8][4];
    {
        int r = wid * 16 + (lane & 7) + ((lane >> 3) & 1) * 8;
        int ch = (lane >> 4) * 8;
#pragma unroll
        for (int kk = 0; kk < 8; kk++) ldsm4(Qf[kk], sm + (r * FSV + ch + kk * 16) * 2);
    }

    float O[16][4];
#pragma unroll
    for (int i = 0; i < 16; i++)
#pragma unroll
        for (int j = 0; j < 4; j++) O[i][j] = 0.f;
    float m0 = -INFINITY, m1 = -INFINITY, l0 = 0.f, l1 = 0.f;

    const int nkv = 2 * qtile + 2;
    const int q0 = qbase + wid * 16 + lr;

    // ldmatrix lane components
    const int kb_row = (lane >> 4) * 8 + (lane & 7);        // K: key row
    const int kb_k = ((lane >> 3) & 1) * 8;                 // K: d offset
    const int v_krow = (lane & 7) + ((lane >> 3) & 1) * 8;  // V: key row within 16
    const int v_dch = (lane >> 4) * 8;                      // V: d chunk offset

    for (int j = 0; j < nkv; j++) {
        CP_WAIT(1);
        __syncthreads();
        if (j + 2 < nkv) prefetchKV(j + 2, (j + 2) % 3);
        cp_commit();

        const int stage = j % 3;
        const uint32_t kB = sm + (Q_HALVES + stage * KV_STAGE_H) * 2;
        const uint32_t vB = sm + (Q_HALVES + (3 + stage) * KV_STAGE_H) * 2;
        const int kv0 = j * 64;

        // S = Q K^T
        float Sa[8][4];
#pragma unroll
        for (int i = 0; i < 8; i++)
#pragma unroll
            for (int t = 0; t < 4; t++) Sa[i][t] = 0.f;
#pragma unroll
        for (int kk = 0; kk < 8; kk++) {
#pragma unroll
            for (int bt = 0; bt < 4; bt++) {
                uint32_t b[4];
                ldsm4(b, kB + ((bt * 16 + kb_row) * FSV + kb_k + kk * 16) * 2);
                mma16816(Sa[2 * bt], Qf[kk], b[0], b[1]);
                mma16816(Sa[2 * bt + 1], Qf[kk], b[2], b[3]);
            }
        }

        // causal mask (only last two kv tiles overlap the diagonal)
        if (j >= nkv - 2) {
#pragma unroll
            for (int nt = 0; nt < 8; nt++) {
                int key = kv0 + nt * 8 + lc * 2;
                if (key > q0) Sa[nt][0] = -INFINITY;
                if (key + 1 > q0) Sa[nt][1] = -INFINITY;
                if (key > q0 + 8) Sa[nt][2] = -INFINITY;
                if (key + 1 > q0 + 8) Sa[nt][3] = -INFINITY;
            }
        }

        // online softmax (fp32)
        float mx0 = -INFINITY, mx1 = -INFINITY;
#pragma unroll
        for (int nt = 0; nt < 8; nt++) {
            mx0 = fmaxf(mx0, fmaxf(Sa[nt][0], Sa[nt][1]));
            mx1 = fmaxf(mx1, fmaxf(Sa[nt][2], Sa[nt][3]));
        }
        mx0 = fmaxf(mx0, __shfl_xor_sync(0xffffffffu, mx0, 1));
        mx0 = fmaxf(mx0, __shfl_xor_sync(0xffffffffu, mx0, 2));
        mx1 = fmaxf(mx1, __shfl_xor_sync(0xffffffffu, mx1, 1));
        mx1 = fmaxf(mx1, __shfl_xor_sync(0xffffffffu, mx1, 2));
        float mn0 = fmaxf(m0, mx0), mn1 = fmaxf(m1, mx1);
        float al0 = __expf(m0 - mn0), al1 = __expf(m1 - mn1);
        m0 = mn0;
        m1 = mn1;
        float rs0 = 0.f, rs1 = 0.f;
#pragma unroll
        for (int nt = 0; nt < 8; nt++) {
            Sa[nt][0] = __expf(Sa[nt][0] - mn0);
            Sa[nt][1] = __expf(Sa[nt][1] - mn0);
            Sa[nt][2] = __expf(Sa[nt][2] - mn1);
            Sa[nt][3] = __expf(Sa[nt][3] - mn1);
            rs0 += Sa[nt][0] + Sa[nt][1];
            rs1 += Sa[nt][2] + Sa[nt][3];
        }
        rs0 += __shfl_xor_sync(0xffffffffu, rs0, 1);
        rs0 += __shfl_xor_sync(0xffffffffu, rs0, 2);
        rs1 += __shfl_xor_sync(0xffffffffu, rs1, 1);
        rs1 += __shfl_xor_sync(0xffffffffu, rs1, 2);
        l0 = l0 * al0 + rs0;
        l1 = l1 * al1 + rs1;
#pragma unroll
        for (int nt = 0; nt < 16; nt++) {
            O[nt][0] *= al0;
            O[nt][1] *= al0;
            O[nt][2] *= al1;
            O[nt][3] *= al1;
        }

        // O += P V  (P packed to fp16 A-fragments directly from registers)
#pragma unroll
        for (int kt = 0; kt < 4; kt++) {
            uint32_t a[4];
            a[0] = packh2(Sa[2 * kt][0], Sa[2 * kt][1]);
            a[1] = packh2(Sa[2 * kt][2], Sa[2 * kt][3]);
            a[2] = packh2(Sa[2 * kt + 1][0], Sa[2 * kt + 1][1]);
            a[3] = packh2(Sa[2 * kt + 1][2], Sa[2 * kt + 1][3]);
#pragma unroll
            for (int bt = 0; bt < 8; bt++) {
                uint32_t b[4];
                ldsm4t(b, vB + ((kt * 16 + v_krow) * FSV + bt * 16 + v_dch) * 2);
                mma16816(O[2 * bt], a, b[0], b[1]);
                mma16816(O[2 * bt + 1], a, b[2], b[3]);
            }
        }
    }

    // normalize + write fp16 to g_attnH [M, D_MODEL], columns h*128+d
    float il0 = 1.f / l0, il1 = 1.f / l1;
    const int hh = bh & (NHEADS - 1);
    const int bb = bh >> 4;
    __half* base0 = g_attnH + ((size_t)(bb * S + q0)) * D_MODEL + hh * DK;
    __half* base1 = base0 + (size_t)8 * D_MODEL;
#pragma unroll
    for (int nt = 0; nt < 16; nt++) {
        int d = nt * 8 + lc * 2;
        *reinterpret_cast<uint32_t*>(base0 + d) = packh2(O[nt][0] * il0, O[nt][1] * il0);
        *reinterpret_cast<uint32_t*>(base1 + d) = packh2(O[nt][2] * il1, O[nt][3] * il1);
    }
}

// ---------------- launch ----------------
extern "C" void kernel_launch(void* const* d_in, const int* in_sizes, int n_in,
                              void* d_out, int out_size) {
    const float* x = (const float*)d_in[0];
    const float* Wq = (const float*)d_in[1];
    const float* Wk = (const float*)d_in[2];
    const float* Wv = (const float*)d_in[3];
    const float* Wo = (const float*)d_in[4];
    const int* pos = (const int*)d_in[5];

    const int S = in_sizes[5];
    const int M = in_sizes[0] / D_MODEL;
    const int B = M / S;

    cudaFuncSetAttribute(gemm_f16_kernel, cudaFuncAttributeMaxDynamicSharedMemorySize, G_SMEM);
    cudaFuncSetAttribute(fa_kernel, cudaFuncAttributeMaxDynamicSharedMemorySize, FA_SMEM);

    // 1) RoPE tables + fp16 conversions
    rope_table_kernel<<<(S * (DK / 2) + 255) / 256, 256>>>(pos, S);
    convert_x_kernel<<<(M * D_MODEL / 4 + 255) / 256, 256>>>(x, M * D_MODEL);
    transpose_w_kernel<<<dim3(64, 64, 4), dim3(32, 8)>>>(Wq, Wk, Wv, Wo);

    // 2) fused QKV projection + RoPE (z selects Q/K/V)
    gemm_f16_kernel<<<dim3(D_MODEL / 128, M / 128, 3), 256, G_SMEM>>>(nullptr, M, S, -1);

    // 3) causal flash attention (longest-first order)
    fa_kernel<<<dim3(S / 128, B * NHEADS), 256, FA_SMEM>>>(S);

    // 4) output projection
    gemm_f16_kernel<<<dim3(D_MODEL / 128, M / 128, 1), 256, G_SMEM>>>((float*)d_out, M, S, 3);
}

// round 10
// speedup vs baseline: 1.1420x; 1.0032x over previous
#include <cuda_runtime.h>
#include <cuda_fp16.h>
#include <cstdint>
#include <math.h>

#define D_MODEL 2048
#define NHEADS 16
#define DK 128
#define MAX_S 2048
#define MAX_M 4096
#define W_ELEMS ((size_t)D_MODEL * D_MODEL)

// ---------------- scratch (static device globals; no allocation) ----------------
__device__ __half g_Wt[4 * W_ELEMS];                 // [4][f][d] transposed fp16 weights (q,k,v,o)
__device__ __half g_xh[(size_t)MAX_M * D_MODEL];     // fp16 copy of x
__device__ __half g_Qh[(size_t)MAX_M * D_MODEL];     // [B,H,S,DK] (scale folded)
__device__ __half g_Kh[(size_t)MAX_M * D_MODEL];
__device__ __half g_Vh[(size_t)MAX_M * D_MODEL];
__device__ __half g_attnH[(size_t)MAX_M * D_MODEL];  // [M, D_MODEL]
__device__ float g_cosT[MAX_S * (DK / 2)];
__device__ float g_sinT[MAX_S * (DK / 2)];

// ---------------- asm helpers ----------------
__device__ __forceinline__ void ldsm4(uint32_t* r, uint32_t addr) {
    asm volatile("ldmatrix.sync.aligned.m8n8.x4.shared.b16 {%0,%1,%2,%3}, [%4];"
                 : "=r"(r[0]), "=r"(r[1]), "=r"(r[2]), "=r"(r[3]) : "r"(addr));
}
__device__ __forceinline__ void ldsm4t(uint32_t* r, uint32_t addr) {
    asm volatile("ldmatrix.sync.aligned.m8n8.x4.trans.shared.b16 {%0,%1,%2,%3}, [%4];"
                 : "=r"(r[0]), "=r"(r[1]), "=r"(r[2]), "=r"(r[3]) : "r"(addr));
}
__device__ __forceinline__ void mma16816(float* d, const uint32_t* a, uint32_t b0, uint32_t b1) {
    asm volatile(
        "mma.sync.aligned.m16n8k16.row.col.f32.f16.f16.f32 "
        "{%0,%1,%2,%3}, {%4,%5,%6,%7}, {%8,%9}, {%0,%1,%2,%3};"
        : "+f"(d[0]), "+f"(d[1]), "+f"(d[2]), "+f"(d[3])
        : "r"(a[0]), "r"(a[1]), "r"(a[2]), "r"(a[3]), "r"(b0), "r"(b1));
}
__device__ __forceinline__ void cp16(uint32_t saddr, const void* gptr) {
    asm volatile("cp.async.cg.shared.global [%0], [%1], 16;" :: "r"(saddr), "l"(gptr));
}
__device__ __forceinline__ void cp_commit() { asm volatile("cp.async.commit_group;"); }
#define CP_WAIT(N) asm volatile("cp.async.wait_group %0;" :: "n"(N))
__device__ __forceinline__ uint32_t packh2(float a, float b) {
    __half2 h = __floats2half2_rn(a, b);
    return *reinterpret_cast<uint32_t*>(&h);
}

// ---------------- RoPE table ----------------
__global__ void rope_table_kernel(const int* __restrict__ pos, int S) {
    int idx = blockIdx.x * blockDim.x + threadIdx.x;
    if (idx >= S * (DK / 2)) return;
    int s = idx / (DK / 2);
    int i = idx % (DK / 2);
    float invf = (float)pow(10000.0, -(double)(2 * i) / (double)DK);
    float ang = (float)pos[s] * invf;
    g_cosT[idx] = cosf(ang);
    g_sinT[idx] = sinf(ang);
}

// ---------------- converters ----------------
__global__ void convert_x_kernel(const float* __restrict__ x, int n) {
    int i = (blockIdx.x * blockDim.x + threadIdx.x) * 4;
    if (i >= n) return;
    float4 v = *reinterpret_cast<const float4*>(x + i);
    uint2 u = {packh2(v.x, v.y), packh2(v.z, v.w)};
    *reinterpret_cast<uint2*>(&g_xh[i]) = u;
}

__global__ void transpose_w_kernel(const float* __restrict__ Wq, const float* __restrict__ Wk,
                                   const float* __restrict__ Wv, const float* __restrict__ Wo) {
    __shared__ float t[32][33];
    const int z = blockIdx.z;
    const float* W = (z == 0) ? Wq : (z == 1) ? Wk : (z == 2) ? Wv : Wo;
    __half* dst = g_Wt + (size_t)z * W_ELEMS;
    int x0 = blockIdx.x * 32, y0 = blockIdx.y * 32;
    int tx = threadIdx.x, ty = threadIdx.y;
#pragma unroll
    for (int i = 0; i < 4; i++)
        t[ty + i * 8][tx] = W[(size_t)(y0 + ty + i * 8) * D_MODEL + x0 + tx];
    __syncthreads();
#pragma unroll
    for (int i = 0; i < 4; i++)
        dst[(size_t)(x0 + ty + i * 8) * D_MODEL + y0 + tx] = __float2half(t[tx][ty + i * 8]);
}

// ---------------- GEMM: 128x128 CTA tile, fp16 mma, 3-stage cp.async ----------------
#define SA 72                       // halves per smem row (64 data + 8 pad); 144B stride
#define G_STAGE_B (128 * SA * 2)    // bytes per matrix per stage (18432)
#define G_SMEM (3 * 2 * G_STAGE_B)  // 110592

__global__ __launch_bounds__(256, 2) void gemm_f16_kernel(float* __restrict__ outF, int M,
                                                          int S, int mode_in) {
    extern __shared__ __align__(16) unsigned char smraw[];
    uint32_t sm = (uint32_t)__cvta_generic_to_shared(smraw);

    const int mode = (mode_in < 0) ? (int)blockIdx.z : mode_in;
    const __half* Ag = (mode_in < 0) ? g_xh : g_attnH;
    const __half* Bg = g_Wt + (size_t)mode * W_ELEMS;  // [n][k] fp16
    const int bm = blockIdx.y * 128;
    const int bn = blockIdx.x * 128;
    const int tid = threadIdx.x;
    const int lane = tid & 31, wid = tid >> 5;
    const int wm = wid & 3, wn = wid >> 2;
    const int lr = lane >> 2, lc = lane & 3;

    const int a_row = (lane & 7) + ((lane >> 3) & 1) * 8;
    const int a_ch = (lane >> 4) * 8;
    const int aoff0 = ((wm * 32 + a_row) * SA + a_ch) * 2;
    const int aoff1 = ((wm * 32 + 16 + a_row) * SA + a_ch) * 2;
    const int b_row = (lane >> 4) * 8 + (lane & 7);
    const int b_k = ((lane >> 3) & 1) * 8;
    const int boff = ((wn * 64 + b_row) * SA + b_k) * 2;

    float acc[2][8][4];
#pragma unroll
    for (int i = 0; i < 2; i++)
#pragma unroll
        for (int j = 0; j < 8; j++)
#pragma unroll
            for (int k = 0; k < 4; k++) acc[i][j][k] = 0.f;

    auto prefetch = [&](int stage, int kt) {
        uint32_t aB = sm + stage * 2 * G_STAGE_B;
        uint32_t bB = aB + G_STAGE_B;
        const __half* Ap = Ag + (size_t)bm * D_MODEL + kt * 64;
        const __half* Bp = Bg + (size_t)bn * D_MODEL + kt * 64;
#pragma unroll
        for (int i = 0; i < 4; i++) {
            int idx = tid + i * 256;
            int r = idx >> 3, c = (idx & 7) * 8;
            cp16(aB + (r * SA + c) * 2, Ap + (size_t)r * D_MODEL + c);
            cp16(bB + (r * SA + c) * 2, Bp + (size_t)r * D_MODEL + c);
        }
    };

    prefetch(0, 0);
    cp_commit();
    prefetch(1, 1);
    cp_commit();

    for (int kt = 0; kt < 32; kt++) {
        CP_WAIT(1);
        __syncthreads();
        if (kt + 2 < 32) prefetch((kt + 2) % 3, kt + 2);
        cp_commit();

        uint32_t aB = sm + (kt % 3) * 2 * G_STAGE_B;
        uint32_t bB = aB + G_STAGE_B;

        uint32_t aF[4][2][4];
#pragma unroll
        for (int kk = 0; kk < 4; kk++) {
            ldsm4(aF[kk][0], aB + aoff0 + kk * 32);
            ldsm4(aF[kk][1], aB + aoff1 + kk * 32);
        }
#pragma unroll
        for (int kk = 0; kk < 4; kk++) {
#pragma unroll
            for (int bt = 0; bt < 4; bt++) {
                uint32_t b[4];
                ldsm4(b, bB + boff + bt * 16 * SA * 2 + kk * 32);
                mma16816(acc[0][2 * bt], aF[kk][0], b[0], b[1]);
                mma16816(acc[1][2 * bt], aF[kk][1], b[0], b[1]);
                mma16816(acc[0][2 * bt + 1], aF[kk][0], b[2], b[3]);
                mma16816(acc[1][2 * bt + 1], aF[kk][1], b[2], b[3]);
            }
        }
    }

#pragma unroll
    for (int mt = 0; mt < 2; mt++) {
#pragma unroll
        for (int nt = 0; nt < 8; nt++) {
#pragma unroll
            for (int half = 0; half < 2; half++) {
                int m = bm + wm * 32 + mt * 16 + lr + half * 8;
                int f = bn + wn * 64 + nt * 8 + lc * 2;
                float c0 = acc[mt][nt][half * 2];
                float c1 = acc[mt][nt][half * 2 + 1];
                if (mode == 3) {
                    *reinterpret_cast<float2*>(outF + (size_t)m * D_MODEL + f) =
                        make_float2(c0, c1);
                } else {
                    int b = m / S, s = m - b * S;
                    int h = f >> 7, d = f & (DK - 1);
                    float o0 = c0, o1 = c1;
                    if (mode < 2) {
                        int i = d >> 1;
                        float cs = g_cosT[s * (DK / 2) + i];
                        float sn = g_sinT[s * (DK / 2) + i];
                        o0 = c0 * cs - c1 * sn;
                        o1 = c0 * sn + c1 * cs;
                        if (mode == 0) {
                            o0 *= 0.08838834764831845f;
                            o1 *= 0.08838834764831845f;
                        }
                    }
                    __half* dst = ((mode == 0) ? g_Qh : (mode == 1) ? g_Kh : g_Vh) +
                                  ((size_t)(b * NHEADS + h) * S + s) * DK + d;
                    *reinterpret_cast<uint32_t*>(dst) = packh2(o0, o1);
                }
            }
        }
    }
}

// ---------------- Flash attention: software-pipelined softmax, 4-stage KV ring ----
#define FSV 136
#define Q_H (128 * FSV)
#define KV_H (64 * FSV)
#define FA_NSTG 4
#define FA_SMEM ((Q_H + FA_NSTG * 2 * KV_H) * 2)  // 174080

__global__ __launch_bounds__(256, 1) void fa_kernel(int S) {
    extern __shared__ __align__(16) unsigned char smraw[];
    uint32_t sm = (uint32_t)__cvta_generic_to_shared(smraw);

    const int bh = blockIdx.y;
    const int qtile = gridDim.x - 1 - blockIdx.x;  // longest-first
    const int qbase = qtile * 128;
    const __half* Qp = g_Qh + (size_t)bh * S * DK;
    const __half* Kp = g_Kh + (size_t)bh * S * DK;
    const __half* Vp = g_Vh + (size_t)bh * S * DK;

    const int tid = threadIdx.x, lane = tid & 31, wid = tid >> 5;
    const int lr = lane >> 2, lc = lane & 3;
    const int nkv = 2 * qtile + 2;  // always even

    const int kb_row = (lane >> 4) * 8 + (lane & 7);
    const int kb_k = ((lane >> 3) & 1) * 8;
    const int v_krow = (lane & 7) + ((lane >> 3) & 1) * 8;
    const int v_dch = (lane >> 4) * 8;

    auto kBase = [&](int stage) { return sm + (Q_H + stage * KV_H) * 2; };
    auto vBase = [&](int stage) { return sm + (Q_H + (FA_NSTG + stage) * KV_H) * 2; };

#pragma unroll
    for (int i = 0; i < 8; i++) {
        int idx = tid + i * 256;
        int r = idx >> 4, c = (idx & 15) * 8;
        cp16(sm + (r * FSV + c) * 2, Qp + (size_t)(qbase + r) * DK + c);
    }
    cp_commit();

    auto prefetchKV = [&](int j) {
        int stage = j & 3;
        uint32_t kB = kBase(stage), vB = vBase(stage);
        const __half* Kt = Kp + (size_t)(j * 64) * DK;
        const __half* Vt = Vp + (size_t)(j * 64) * DK;
#pragma unroll
        for (int i = 0; i < 4; i++) {
            int idx = tid + i * 256;
            int r = idx >> 4, c = (idx & 15) * 8;
            cp16(kB + (r * FSV + c) * 2, Kt + (size_t)r * DK + c);
            cp16(vB + (r * FSV + c) * 2, Vt + (size_t)r * DK + c);
        }
    };

#pragma unroll
    for (int jp = 0; jp < 3; jp++) {
        if (jp < nkv) prefetchKV(jp);
        cp_commit();
    }

    CP_WAIT(2);  // Q + stage0 resident
    __syncthreads();

    uint32_t Qf[8][4];
    {
        int r = wid * 16 + (lane & 7) + ((lane >> 3) & 1) * 8;
        int ch = (lane >> 4) * 8;
#pragma unroll
        for (int kk = 0; kk < 8; kk++) ldsm4(Qf[kk], sm + (r * FSV + ch + kk * 16) * 2);
    }

    auto computeQK = [&](int stage, float (*Sa)[4]) {
        uint32_t kB = kBase(stage);
#pragma unroll
        for (int i = 0; i < 8; i++)
#pragma unroll
            for (int t = 0; t < 4; t++) Sa[i][t] = 0.f;
#pragma unroll
        for (int kk = 0; kk < 8; kk++) {
#pragma unroll
            for (int bt = 0; bt < 4; bt++) {
                uint32_t b[4];
                ldsm4(b, kB + ((bt * 16 + kb_row) * FSV + kb_k + kk * 16) * 2);
                mma16816(Sa[2 * bt], Qf[kk], b[0], b[1]);
                mma16816(Sa[2 * bt + 1], Qf[kk], b[2], b[3]);
            }
        }
    };

    float O[16][4];
#pragma unroll
    for (int i = 0; i < 16; i++)
#pragma unroll
        for (int j = 0; j < 4; j++) O[i][j] = 0.f;
    float m0 = -INFINITY, m1 = -INFINITY, l0 = 0.f, l1 = 0.f;
    const int q0 = qbase + wid * 16 + lr;

    float SaA[8][4], SaB[8][4];
    computeQK(0, SaA);  // scores for tile 0 (raw; masked at consume time)

#define FA_STEP(jj, cur, nxt)                                                     \
    {                                                                             \
        CP_WAIT(1);                                                               \
        __syncthreads();                                                          \
        if ((jj) + 3 < nkv) prefetchKV((jj) + 3);                                 \
        cp_commit();                                                              \
        if ((jj) + 1 < nkv) computeQK(((jj) + 1) & 3, nxt);                       \
        const int kv0 = (jj) * 64;                                                \
        if ((jj) >= nkv - 2) {                                                    \
            _Pragma("unroll") for (int nt = 0; nt < 8; nt++) {                    \
                int key = kv0 + nt * 8 + lc * 2;                                  \
                if (key > q0) cur[nt][0] = -INFINITY;                             \
                if (key + 1 > q0) cur[nt][1] = -INFINITY;                         \
                if (key > q0 + 8) cur[nt][2] = -INFINITY;                         \
                if (key + 1 > q0 + 8) cur[nt][3] = -INFINITY;                     \
            }                                                                     \
        }                                                                         \
        float mx0 = -INFINITY, mx1 = -INFINITY;                                   \
        _Pragma("unroll") for (int nt = 0; nt < 8; nt++) {                        \
            mx0 = fmaxf(mx0, fmaxf(cur[nt][0], cur[nt][1]));                      \
            mx1 = fmaxf(mx1, fmaxf(cur[nt][2], cur[nt][3]));                      \
        }                                                                         \
        mx0 = fmaxf(mx0, __shfl_xor_sync(0xffffffffu, mx0, 1));                   \
        mx0 = fmaxf(mx0, __shfl_xor_sync(0xffffffffu, mx0, 2));                   \
        mx1 = fmaxf(mx1, __shfl_xor_sync(0xffffffffu, mx1, 1));                   \
        mx1 = fmaxf(mx1, __shfl_xor_sync(0xffffffffu, mx1, 2));                   \
        float mn0 = fmaxf(m0, mx0), mn1 = fmaxf(m1, mx1);                         \
        float al0 = __expf(m0 - mn0), al1 = __expf(m1 - mn1);                     \
        m0 = mn0;                                                                 \
        m1 = mn1;                                                                 \
        float rs0 = 0.f, rs1 = 0.f;                                               \
        _Pragma("unroll") for (int nt = 0; nt < 8; nt++) {                        \
            cur[nt][0] = __expf(cur[nt][0] - mn0);                                \
            cur[nt][1] = __expf(cur[nt][1] - mn0);                                \
            cur[nt][2] = __expf(cur[nt][2] - mn1);                                \
            cur[nt][3] = __expf(cur[nt][3] - mn1);                                \
            rs0 += cur[nt][0] + cur[nt][1];                                       \
            rs1 += cur[nt][2] + cur[nt][3];                                       \
        }                                                                         \
        rs0 += __shfl_xor_sync(0xffffffffu, rs0, 1);                              \
        rs0 += __shfl_xor_sync(0xffffffffu, rs0, 2);                              \
        rs1 += __shfl_xor_sync(0xffffffffu, rs1, 1);                              \
        rs1 += __shfl_xor_sync(0xffffffffu, rs1, 2);                              \
        l0 = l0 * al0 + rs0;                                                      \
        l1 = l1 * al1 + rs1;                                                      \
        _Pragma("unroll") for (int nt = 0; nt < 16; nt++) {                       \
            O[nt][0] *= al0;                                                      \
            O[nt][1] *= al0;                                                      \
            O[nt][2] *= al1;                                                      \
            O[nt][3] *= al1;                                                      \
        }                                                                         \
        uint32_t vB = vBase((jj) & 3);                                            \
        _Pragma("unroll") for (int kt = 0; kt < 4; kt++) {                        \
            uint32_t a[4];                                                        \
            a[0] = packh2(cur[2 * kt][0], cur[2 * kt][1]);                        \
            a[1] = packh2(cur[2 * kt][2], cur[2 * kt][3]);                        \
            a[2] = packh2(cur[2 * kt + 1][0], cur[2 * kt + 1][1]);                \
            a[3] = packh2(cur[2 * kt + 1][2], cur[2 * kt + 1][3]);                \
            _Pragma("unroll") for (int bt = 0; bt < 8; bt++) {                    \
                uint32_t b[4];                                                    \
                ldsm4t(b, vB + ((kt * 16 + v_krow) * FSV + bt * 16 + v_dch) * 2); \
                mma16816(O[2 * bt], a, b[0], b[1]);                               \
                mma16816(O[2 * bt + 1], a, b[2], b[3]);                           \
            }                                                                     \
        }                                                                         \
    }

    for (int j = 0; j < nkv; j += 2) {
        FA_STEP(j, SaA, SaB);
        FA_STEP(j + 1, SaB, SaA);
    }

    float il0 = 1.f / l0, il1 = 1.f / l1;
    const int hh = bh & (NHEADS - 1);
    const int bb = bh >> 4;
    __half* base0 = g_attnH + ((size_t)(bb * S + q0)) * D_MODEL + hh * DK;
    __half* base1 = base0 + (size_t)8 * D_MODEL;
#pragma unroll
    for (int nt = 0; nt < 16; nt++) {
        int d = nt * 8 + lc * 2;
        *reinterpret_cast<uint32_t*>(base0 + d) = packh2(O[nt][0] * il0, O[nt][1] * il0);
        *reinterpret_cast<uint32_t*>(base1 + d) = packh2(O[nt][2] * il1, O[nt][3] * il1);
    }
}

// ---------------- launch ----------------
extern "C" void kernel_launch(void* const* d_in, const int* in_sizes, int n_in,
                              void* d_out, int out_size) {
    const float* x = (const float*)d_in[0];
    const float* Wq = (const float*)d_in[1];
    const float* Wk = (const float*)d_in[2];
    const float* Wv = (const float*)d_in[3];
    const float* Wo = (const float*)d_in[4];
    const int* pos = (const int*)d_in[5];

    const int S = in_sizes[5];
    const int M = in_sizes[0] / D_MODEL;
    const int B = M / S;

    cudaFuncSetAttribute(gemm_f16_kernel, cudaFuncAttributeMaxDynamicSharedMemorySize, G_SMEM);
    cudaFuncSetAttribute(fa_kernel, cudaFuncAttributeMaxDynamicSharedMemorySize, FA_SMEM);

    rope_table_kernel<<<(S * (DK / 2) + 255) / 256, 256>>>(pos, S);
    convert_x_kernel<<<(M * D_MODEL / 4 + 255) / 256, 256>>>(x, M * D_MODEL);
    transpose_w_kernel<<<dim3(64, 64, 4), dim3(32, 8)>>>(Wq, Wk, Wv, Wo);

    gemm_f16_kernel<<<dim3(D_MODEL / 128, M / 128, 3), 256, G_SMEM>>>(nullptr, M, S, -1);

    fa_kernel<<<dim3(S / 128, B * NHEADS), 256, FA_SMEM>>>(S);

    gemm_f16_kernel<<<dim3(D_MODEL / 128, M / 128, 1), 256, G_SMEM>>>((float*)d_out, M, S, 3);
}